// round 16
// baseline (speedup 1.0000x reference)
#include <cuda_runtime.h>
#include <cuda_fp16.h>
#include <cstdint>

#define N_NODES 100000
#define E_EDGES 200000
#define SDIM 128
#define CDIM 768
#define KTOT 896
#define NC 320        // 192 chem + 128 comb
#define NS 64

// ---------------- scratch (static device globals; no allocation) ----------------
__device__ __align__(16) __half g_SP[(size_t)E_EDGES * SDIM];   // fp16 products
__device__ __align__(16) __half g_CP[(size_t)E_EDGES * CDIM];
__device__ float g_ss[E_EDGES];
__device__ float g_acc[E_EDGES];
__device__ int   g_outidx[E_EDGES];
__device__ unsigned char g_valid[E_EDGES];
__device__ __align__(16) __half g_WC[NC * KTOT];    // [n][k] K-major fp16
__device__ __align__(16) __half g_WS[NS * SDIM];
__device__ float g_bC[NC], g_v2[NC], g_bS[NS];
__device__ int   g_count;

// ---------------- helpers ----------------
__device__ __forceinline__ uint32_t smem_u32(const void* p) {
    uint32_t a;
    asm("{ .reg .u64 t; cvta.to.shared.u64 t, %1; cvt.u32.u64 %0, t; }" : "=r"(a) : "l"(p));
    return a;
}
__device__ __forceinline__ void cp16(uint32_t dst, const void* src) {
    asm volatile("cp.async.cg.shared.global [%0], [%1], 16;" :: "r"(dst), "l"(src) : "memory");
}
#define CP_COMMIT() asm volatile("cp.async.commit_group;" ::: "memory")
#define CP_WAIT0()  asm volatile("cp.async.wait_group 0;" ::: "memory")
#define CP_WAIT1()  asm volatile("cp.async.wait_group 1;" ::: "memory")

__device__ __forceinline__ void ldm_x4(uint32_t r[4], uint32_t addr) {
    asm volatile("ldmatrix.sync.aligned.m8n8.x4.shared.b16 {%0,%1,%2,%3}, [%4];"
        : "=r"(r[0]), "=r"(r[1]), "=r"(r[2]), "=r"(r[3]) : "r"(addr));
}
__device__ __forceinline__ void mma_f16(float c[4], const uint32_t a[4], const uint32_t b[2]) {
    asm volatile(
        "mma.sync.aligned.m16n8k16.row.col.f32.f16.f16.f32 "
        "{%0,%1,%2,%3}, {%4,%5,%6,%7}, {%8,%9}, {%0,%1,%2,%3};"
        : "+f"(c[0]), "+f"(c[1]), "+f"(c[2]), "+f"(c[3])
        : "r"(a[0]), "r"(a[1]), "r"(a[2]), "r"(a[3]), "r"(b[0]), "r"(b[1]));
}

__device__ __forceinline__ void softmax3(const float* pw, float& w0, float& w1, float& w2) {
    float p0 = pw[0], p1 = pw[1], p2 = pw[2];
    float m = fmaxf(p0, fmaxf(p1, p2));
    float e0 = expf(p0 - m), e1 = expf(p1 - m), e2 = expf(p2 - m);
    float s = e0 + e1 + e2;
    w0 = e0 / s; w1 = e1 / s; w2 = e2 / s;
}
// int64-vs-int32 edge detection (ids < 2^31 -> int64 high words all zero)
__device__ __forceinline__ int detect64(const void* edge) {
    const unsigned* ew = (const unsigned*)edge;
    unsigned hi = 0;
    #pragma unroll
    for (int i = 0; i < 16; i++) hi |= ew[2 * i + 1];
    return hi == 0u;
}
__device__ __forceinline__ void read_edge(const void* edge, int is64, int e, int& s, int& d) {
    if (is64) {
        const long long* p = (const long long*)edge;
        s = (int)p[2 * e]; d = (int)p[2 * e + 1];
    } else {
        const int* p = (const int*)edge;
        s = p[2 * e]; d = p[2 * e + 1];
    }
}
__device__ __forceinline__ uint2 h4_pack(const float4& p) {
    __half2 a = __floats2half2_rn(p.x, p.y);
    __half2 b = __floats2half2_rn(p.z, p.w);
    return make_uint2(*reinterpret_cast<unsigned*>(&a), *reinterpret_cast<unsigned*>(&b));
}

// ---------------- kernel: reset counter ----------------
__global__ void k_zero() { if (threadIdx.x == 0) g_count = 0; }

// ---------------- kernel: pack weights (transposed [n][k], fp16) ----------------
__global__ void k_pack(const float* __restrict__ cw1, const float* __restrict__ cb1,
                       const float* __restrict__ cw2,
                       const float* __restrict__ mw1, const float* __restrict__ mb1,
                       const float* __restrict__ mw2,
                       const float* __restrict__ sw1, const float* __restrict__ sb1,
                       const float* __restrict__ pw)
{
    int idx = blockIdx.x * blockDim.x + threadIdx.x;
    const int totC = NC * KTOT;
    if (idx < totC) {
        int n = idx / KTOT, k = idx % KTOT;
        float v;
        if (n < 192) v = (k >= SDIM) ? cw1[(k - SDIM) * 192 + n] : 0.0f;
        else         v = mw1[k * 128 + (n - 192)];
        g_WC[idx] = __float2half_rn(v);
    }
    int idx2 = idx - totC;
    if (idx2 >= 0 && idx2 < NS * SDIM) {
        int n = idx2 / SDIM, k = idx2 % SDIM;
        g_WS[idx2] = __float2half_rn(sw1[k * NS + n]);
    }
    if (idx < NC) {
        g_bC[idx] = (idx < 192) ? cb1[idx] : mb1[idx - 192];
        float w0, w1, w2; softmax3(pw, w0, w1, w2);
        g_v2[idx] = (idx < 192) ? w1 * cw2[idx] : w2 * mw2[idx - 192];
    }
    if (idx < NS) g_bS[idx] = sb1[idx];
}

// ---------------- kernel: merged gather (SP all edges, CP for valid slots) ------
__global__ void k_gather(const float* __restrict__ z, const float* __restrict__ chem,
                         const void* __restrict__ edge, const int* __restrict__ mask)
{
    int w = (blockIdx.x * blockDim.x + threadIdx.x) >> 5;
    int lane = threadIdx.x & 31;
    if (w >= E_EDGES) return;

    int src = 0, dst = 0, valid = 0;
    if (lane == 0) {
        int is64 = detect64(edge);
        read_edge(edge, is64, w, src, dst);
        valid = (mask[src] != 0) && (mask[dst] != 0);
        g_valid[w] = (unsigned char)valid;
    }
    src = __shfl_sync(0xffffffffu, src, 0);
    dst = __shfl_sync(0xffffffffu, dst, 0);
    valid = __shfl_sync(0xffffffffu, valid, 0);

    float4 zs = *(const float4*)&z[(size_t)src * SDIM + lane * 4];
    float4 zd = *(const float4*)&z[(size_t)dst * SDIM + lane * 4];
    float4 p;
    p.x = zs.x * zd.x; p.y = zs.y * zd.y; p.z = zs.z * zd.z; p.w = zs.w * zd.w;
    *(uint2*)&g_SP[(size_t)w * SDIM + lane * 4] = h4_pack(p);

    if (!valid) return;

    int slot = 0;
    if (lane == 0) slot = atomicAdd(&g_count, 1);
    slot = __shfl_sync(0xffffffffu, slot, 0);
    if (lane == 0) { g_outidx[slot] = w; g_acc[slot] = 0.0f; }

    size_t cp = (size_t)slot * CDIM;
    #pragma unroll
    for (int i = 0; i < 6; i++) {
        int col = (lane + 32 * i) * 4;
        float4 cs = *(const float4*)&chem[(size_t)src * CDIM + col];
        float4 cd = *(const float4*)&chem[(size_t)dst * CDIM + col];
        float4 c;
        c.x = cs.x * cd.x; c.y = cs.y * cd.y; c.z = cs.z * cd.z; c.w = cs.w * cd.w;
        *(uint2*)&g_CP[cp + col] = h4_pack(c);
    }
}

// ---------------- merged HMMA fp16 GEMM (BM=128, BN=64, BK=64, 8 warps) ---------
// Warp tile 32x32; 4 k16 steps per chunk; half the barriers of BK=32.
// Row stride 144B (36 u32): rows start at bank 4r mod 32 -> ldmatrix conflict-free.
// blockIdx.x < 5 : combined (A=[SP via oidx | CP], K=896, B=g_WC, n0=x*64) -> g_acc
// blockIdx.x == 5: structural (A=g_SP, K=128, B=g_WS) -> g_ss / out
#define AROW 36
#define AS_P (128 * AROW)    // 4608 u32 per A stage
#define BS_P (64 * AROW)     // 2304 u32 per B stage
#define AS_B (AS_P * 4)
#define BS_B (BS_P * 4)
#define SMEM_U32 (3 * AS_P + 3 * BS_P + 128 + 128)
#define SMEM_BYTES (SMEM_U32 * 4)

__global__ void __launch_bounds__(256, 2) k_gemm(const float* __restrict__ sw2,
                                                 const float* __restrict__ sb2,
                                                 float* __restrict__ out)
{
    extern __shared__ uint32_t S[];
    uint32_t* Abase = S;
    uint32_t* Bbase = S + 3 * AS_P;
    float* rs = (float*)(S + 3 * AS_P + 3 * BS_P);
    int* oidx = (int*)(rs + 128);

    int tid = threadIdx.x, lane = tid & 31, wid = tid >> 5;
    int g = lane >> 2, tg = lane & 3;
    int wm = wid >> 1, wn = wid & 1;     // 4 row-groups (32 rows) x 2 col-groups

    const bool comb = (blockIdx.x < 5);
    int M, m0, n0, KCH;
    int m0raw = blockIdx.y * 128;
    if (comb) {
        M = g_count; m0 = m0raw;
        if (m0 >= M) return;
        n0 = blockIdx.x * 64; KCH = KTOT / 64;   // 14
    } else {
        M = E_EDGES; m0 = m0raw; n0 = 0; KCH = SDIM / 64;  // 2
    }

    if (tid < 128) {
        rs[tid] = 0.0f;
        if (comb) { int r = m0 + tid; oidx[tid] = (r < M) ? g_outidx[r] : g_outidx[0]; }
    }
    __syncthreads();

    uint32_t sA = smem_u32(Abase);
    uint32_t sB = smem_u32(Bbase);

    // ---- hoisted load assignments; running pointers advance 64 halfs per chunk
    // A: 128 rows x 8 16B-units = 1024 cp16 -> 4 per thread
    uint32_t aDst[4];
    const __half* aCur[4];
    const __half* aPtrC[4];
    #pragma unroll
    for (int i = 0; i < 4; i++) {
        int id = tid + i * 256;
        int row = id >> 3, u = id & 7;
        aDst[i] = sA + (row * AROW + u * 4) * 4;
        if (!comb) {
            int r = m0 + row; if (r >= E_EDGES) r = E_EDGES - 1;
            aCur[i] = g_SP + (size_t)r * SDIM + u * 8;
            aPtrC[i] = aCur[i];
        } else {
            aCur[i] = g_SP + (size_t)oidx[row] * SDIM + u * 8;
            int r = m0 + row; if (r >= M) r = 0;
            aPtrC[i] = g_CP + (size_t)r * CDIM + u * 8;
        }
    }
    // B: 64 rows x 8 units = 512 cp16 -> 2 per thread
    uint32_t bDst[2];
    const __half* bCur[2];
    #pragma unroll
    for (int i = 0; i < 2; i++) {
        int id = tid + i * 256;
        int row = id >> 3, u = id & 7;
        bDst[i] = sB + (row * AROW + u * 4) * 4;
        bCur[i] = (!comb) ? (g_WS + (size_t)row * SDIM + u * 8)
                          : (g_WC + (size_t)(n0 + row) * KTOT + u * 8);
    }

    auto prefetch = [&](int c, int buf) {
        if (comb && c == 2) {
            #pragma unroll
            for (int i = 0; i < 4; i++) aCur[i] = aPtrC[i];
        }
        #pragma unroll
        for (int i = 0; i < 4; i++) {
            cp16(aDst[i] + (uint32_t)buf * AS_B, aCur[i]);
            aCur[i] += 64;
        }
        #pragma unroll
        for (int i = 0; i < 2; i++) {
            cp16(bDst[i] + (uint32_t)buf * BS_B, bCur[i]);
            bCur[i] += 64;
        }
        CP_COMMIT();
    };

    // ldmatrix lane addresses (144B row stride)
    uint32_t aAddr = sA + (uint32_t)(wm * 32 + (lane & 15)) * 144 + ((lane >> 4) << 4);
    uint32_t bAddr = sB + (uint32_t)(wn * 32 + (lane & 7) + ((lane >> 4) << 3)) * 144
                        + (((lane >> 3) & 1) << 4);

    float acc[2][4][4];
    #pragma unroll
    for (int mi = 0; mi < 2; mi++)
        #pragma unroll
        for (int ni = 0; ni < 4; ni++)
            #pragma unroll
            for (int j = 0; j < 4; j++) acc[mi][ni][j] = 0.0f;

    prefetch(0, 0);
    if (KCH > 1) prefetch(1, 1);

    int bc = 0;   // buffer of current chunk
    for (int c = 0; c < KCH; c++) {
        if (c + 1 < KCH) CP_WAIT1(); else CP_WAIT0();
        __syncthreads();
        if (c + 2 < KCH) {
            int b2 = bc + 2; if (b2 >= 3) b2 -= 3;
            prefetch(c + 2, b2);
        }

        uint32_t aOff = (uint32_t)bc * AS_B;
        uint32_t bOff = (uint32_t)bc * BS_B;

        #pragma unroll
        for (int k16 = 0; k16 < 4; k16++) {
            uint32_t ka = aOff + k16 * 32;
            uint32_t kb = bOff + k16 * 32;
            uint32_t ah[2][4], bh[4][2];
            ldm_x4(ah[0], aAddr + ka);
            ldm_x4(ah[1], aAddr + ka + 16 * 144);
            ldm_x4(&bh[0][0], bAddr + kb);
            ldm_x4(&bh[2][0], bAddr + kb + 16 * 144);
            #pragma unroll
            for (int mi = 0; mi < 2; mi++)
                #pragma unroll
                for (int ni = 0; ni < 4; ni++)
                    mma_f16(acc[mi][ni], ah[mi], bh[ni]);
        }
        if (++bc == 3) bc = 0;
    }
    __syncthreads();

    // fused epilogue: relu(x + bias) dot weight-vector, reduced to per-row sums
    const float* bb = comb ? g_bC : g_bS;
    const float* vv = comb ? g_v2 : sw2;
    #pragma unroll
    for (int mi = 0; mi < 2; mi++) {
        float r0 = 0.f, r1 = 0.f;
        #pragma unroll
        for (int ni = 0; ni < 4; ni++) {
            int col = n0 + wn * 32 + ni * 8 + 2 * tg;
            float b0 = bb[col], b1 = bb[col + 1];
            float v0 = vv[col], v1 = vv[col + 1];
            r0 += fmaxf(acc[mi][ni][0] + b0, 0.f) * v0 + fmaxf(acc[mi][ni][1] + b1, 0.f) * v1;
            r1 += fmaxf(acc[mi][ni][2] + b0, 0.f) * v0 + fmaxf(acc[mi][ni][3] + b1, 0.f) * v1;
        }
        r0 += __shfl_xor_sync(0xffffffffu, r0, 1);
        r0 += __shfl_xor_sync(0xffffffffu, r0, 2);
        r1 += __shfl_xor_sync(0xffffffffu, r1, 1);
        r1 += __shfl_xor_sync(0xffffffffu, r1, 2);
        if (tg == 0) {
            atomicAdd(&rs[wm * 32 + mi * 16 + g], r0);
            atomicAdd(&rs[wm * 32 + mi * 16 + g + 8], r1);
        }
    }
    __syncthreads();

    if (tid < 128) {
        int row = m0 + tid;
        if (!comb) {
            if (row < E_EDGES) {
                float ss = rs[tid] + sb2[0];
                g_ss[row] = ss;
                if (!g_valid[row]) out[row] = ss;
            }
        } else {
            if (row < M) atomicAdd(&g_acc[row], rs[tid]);
        }
    }
}

// ---------------- final blend for valid edges ----------------
__global__ void k_final(const float* __restrict__ pw, const float* __restrict__ cb2,
                        const float* __restrict__ mb2, float* __restrict__ out)
{
    int idx = blockIdx.x * blockDim.x + threadIdx.x;
    if (idx >= g_count) return;
    float w0, w1, w2; softmax3(pw, w0, w1, w2);
    int e = g_outidx[idx];
    out[e] = w0 * g_ss[e] + g_acc[idx] + w1 * cb2[0] + w2 * mb2[0];
}

// ---------------- launcher (pack forked beside gather; single join) -------------
static cudaStream_t s_side = nullptr;
static cudaEvent_t s_e0 = nullptr, s_ePack = nullptr;

extern "C" void kernel_launch(void* const* d_in, const int* in_sizes, int n_in,
                              void* d_out, int out_size)
{
    const float* z    = (const float*)d_in[0];
    const float* chem = (const float*)d_in[1];
    const void*  edge = d_in[2];
    const int*   mask = (const int*)d_in[3];
    const float* sw1 = (const float*)d_in[4];
    const float* sb1 = (const float*)d_in[5];
    const float* sw2 = (const float*)d_in[6];
    const float* sb2 = (const float*)d_in[7];
    const float* cw1 = (const float*)d_in[8];
    const float* cb1 = (const float*)d_in[9];
    const float* cw2 = (const float*)d_in[10];
    const float* cb2 = (const float*)d_in[11];
    const float* mw1 = (const float*)d_in[12];
    const float* mb1 = (const float*)d_in[13];
    const float* mw2 = (const float*)d_in[14];
    const float* mb2 = (const float*)d_in[15];
    const float* pw  = (const float*)d_in[16];
    float* out = (float*)d_out;

    if (!s_side) {
        cudaStreamCreateWithFlags(&s_side, cudaStreamNonBlocking);
        cudaEventCreateWithFlags(&s_e0, cudaEventDisableTiming);
        cudaEventCreateWithFlags(&s_ePack, cudaEventDisableTiming);
        cudaFuncSetAttribute(k_gemm, cudaFuncAttributeMaxDynamicSharedMemorySize, SMEM_BYTES);
    }

    const int mtiles = (E_EDGES + 127) / 128;  // 1563
    cudaStream_t s0 = 0;

    k_zero<<<1, 32, 0, s0>>>();
    cudaEventRecord(s_e0, s0);

    // side stream: weight pack, concurrent with the DRAM-bound gather
    cudaStreamWaitEvent(s_side, s_e0, 0);
    k_pack<<<1152, 256, 0, s_side>>>(cw1, cb1, cw2, mw1, mb1, mw2, sw1, sb1, pw);
    cudaEventRecord(s_ePack, s_side);

    // main stream: merged gather
    k_gather<<<(E_EDGES + 7) / 8, 256, 0, s0>>>(z, chem, edge, mask);

    // join, then merged GEMM + final
    cudaStreamWaitEvent(s0, s_ePack, 0);
    k_gemm<<<dim3(6, mtiles), 256, SMEM_BYTES, s0>>>(sw2, sb2, out);
    k_final<<<(E_EDGES + 255) / 256, 256, 0, s0>>>(pw, cb2, mb2, out);
}

// round 17
// speedup vs baseline: 1.0766x; 1.0766x over previous
#include <cuda_runtime.h>
#include <cuda_fp16.h>
#include <cstdint>

#define N_NODES 100000
#define E_EDGES 200000
#define SDIM 128
#define CDIM 768
#define KTOT 896
#define NC 320        // 192 chem + 128 comb
#define NS 64

// ---------------- scratch (static device globals; no allocation) ----------------
__device__ __align__(16) __half g_SP[(size_t)E_EDGES * SDIM];   // fp16 products
__device__ __align__(16) __half g_CP[(size_t)E_EDGES * CDIM];
__device__ float g_ss[E_EDGES];
__device__ float g_acc[E_EDGES];
__device__ int   g_outidx[E_EDGES];
__device__ unsigned char g_valid[E_EDGES];
__device__ __align__(16) __half g_WC[NC * KTOT];    // [n][k] K-major fp16
__device__ __align__(16) __half g_WS[NS * SDIM];
__device__ float g_bC[NC], g_v2[NC], g_bS[NS];
__device__ int   g_count;
__device__ int   g_is64;

// ---------------- helpers ----------------
__device__ __forceinline__ uint32_t smem_u32(const void* p) {
    uint32_t a;
    asm("{ .reg .u64 t; cvta.to.shared.u64 t, %1; cvt.u32.u64 %0, t; }" : "=r"(a) : "l"(p));
    return a;
}
__device__ __forceinline__ void cp16(uint32_t dst, const void* src) {
    asm volatile("cp.async.cg.shared.global [%0], [%1], 16;" :: "r"(dst), "l"(src) : "memory");
}
#define CP_COMMIT() asm volatile("cp.async.commit_group;" ::: "memory")
#define CP_WAIT0()  asm volatile("cp.async.wait_group 0;" ::: "memory")
#define CP_WAIT1()  asm volatile("cp.async.wait_group 1;" ::: "memory")

__device__ __forceinline__ void ldm_x4(uint32_t r[4], uint32_t addr) {
    asm volatile("ldmatrix.sync.aligned.m8n8.x4.shared.b16 {%0,%1,%2,%3}, [%4];"
        : "=r"(r[0]), "=r"(r[1]), "=r"(r[2]), "=r"(r[3]) : "r"(addr));
}
__device__ __forceinline__ void mma_f16(float c[4], const uint32_t a[4], const uint32_t b[2]) {
    asm volatile(
        "mma.sync.aligned.m16n8k16.row.col.f32.f16.f16.f32 "
        "{%0,%1,%2,%3}, {%4,%5,%6,%7}, {%8,%9}, {%0,%1,%2,%3};"
        : "+f"(c[0]), "+f"(c[1]), "+f"(c[2]), "+f"(c[3])
        : "r"(a[0]), "r"(a[1]), "r"(a[2]), "r"(a[3]), "r"(b[0]), "r"(b[1]));
}

__device__ __forceinline__ void softmax3(const float* pw, float& w0, float& w1, float& w2) {
    float p0 = pw[0], p1 = pw[1], p2 = pw[2];
    float m = fmaxf(p0, fmaxf(p1, p2));
    float e0 = expf(p0 - m), e1 = expf(p1 - m), e2 = expf(p2 - m);
    float s = e0 + e1 + e2;
    w0 = e0 / s; w1 = e1 / s; w2 = e2 / s;
}
__device__ __forceinline__ void read_edge(const void* edge, int is64, int e, int& s, int& d) {
    if (is64) {
        const long long* p = (const long long*)edge;
        s = (int)p[2 * e]; d = (int)p[2 * e + 1];
    } else {
        const int* p = (const int*)edge;
        s = p[2 * e]; d = p[2 * e + 1];
    }
}
__device__ __forceinline__ uint2 h4_pack(const float4& p) {
    __half2 a = __floats2half2_rn(p.x, p.y);
    __half2 b = __floats2half2_rn(p.z, p.w);
    return make_uint2(*reinterpret_cast<unsigned*>(&a), *reinterpret_cast<unsigned*>(&b));
}

// ---------------- kernel: reset counter + edge dtype detection ----------------
__global__ void k_zero(const void* __restrict__ edge) {
    if (threadIdx.x == 0) {
        g_count = 0;
        const unsigned* ew = (const unsigned*)edge;
        unsigned hi = 0;
        #pragma unroll
        for (int i = 0; i < 16; i++) hi |= ew[2 * i + 1];
        g_is64 = (hi == 0u) ? 1 : 0;
    }
}

// ---------------- kernel: pack weights (transposed [n][k], fp16) ----------------
__global__ void k_pack(const float* __restrict__ cw1, const float* __restrict__ cb1,
                       const float* __restrict__ cw2,
                       const float* __restrict__ mw1, const float* __restrict__ mb1,
                       const float* __restrict__ mw2,
                       const float* __restrict__ sw1, const float* __restrict__ sb1,
                       const float* __restrict__ pw)
{
    int idx = blockIdx.x * blockDim.x + threadIdx.x;
    const int totC = NC * KTOT;
    if (idx < totC) {
        int n = idx / KTOT, k = idx % KTOT;
        float v;
        if (n < 192) v = (k >= SDIM) ? cw1[(k - SDIM) * 192 + n] : 0.0f;
        else         v = mw1[k * 128 + (n - 192)];
        g_WC[idx] = __float2half_rn(v);
    }
    int idx2 = idx - totC;
    if (idx2 >= 0 && idx2 < NS * SDIM) {
        int n = idx2 / SDIM, k = idx2 % SDIM;
        g_WS[idx2] = __float2half_rn(sw1[k * NS + n]);
    }
    if (idx < NC) {
        g_bC[idx] = (idx < 192) ? cb1[idx] : mb1[idx - 192];
        float w0, w1, w2; softmax3(pw, w0, w1, w2);
        g_v2[idx] = (idx < 192) ? w1 * cw2[idx] : w2 * mw2[idx - 192];
    }
    if (idx < NS) g_bS[idx] = sb1[idx];
}

// ---------------- kernel: merged gather (SP all edges, CP for valid slots) ------
__global__ void k_gather(const float* __restrict__ z, const float* __restrict__ chem,
                         const void* __restrict__ edge, const int* __restrict__ mask)
{
    int w = (blockIdx.x * blockDim.x + threadIdx.x) >> 5;
    int lane = threadIdx.x & 31;
    if (w >= E_EDGES) return;

    int src = 0, dst = 0, valid = 0;
    if (lane == 0) {
        read_edge(edge, g_is64, w, src, dst);
        valid = (mask[src] != 0) && (mask[dst] != 0);
        g_valid[w] = (unsigned char)valid;
    }
    src = __shfl_sync(0xffffffffu, src, 0);
    dst = __shfl_sync(0xffffffffu, dst, 0);
    valid = __shfl_sync(0xffffffffu, valid, 0);

    float4 zs = *(const float4*)&z[(size_t)src * SDIM + lane * 4];
    float4 zd = *(const float4*)&z[(size_t)dst * SDIM + lane * 4];
    float4 p;
    p.x = zs.x * zd.x; p.y = zs.y * zd.y; p.z = zs.z * zd.z; p.w = zs.w * zd.w;
    *(uint2*)&g_SP[(size_t)w * SDIM + lane * 4] = h4_pack(p);

    if (!valid) return;

    int slot = 0;
    if (lane == 0) slot = atomicAdd(&g_count, 1);
    slot = __shfl_sync(0xffffffffu, slot, 0);
    if (lane == 0) { g_outidx[slot] = w; g_acc[slot] = 0.0f; }

    size_t cp = (size_t)slot * CDIM;
    #pragma unroll
    for (int i = 0; i < 6; i++) {
        int col = (lane + 32 * i) * 4;
        float4 cs = *(const float4*)&chem[(size_t)src * CDIM + col];
        float4 cd = *(const float4*)&chem[(size_t)dst * CDIM + col];
        float4 c;
        c.x = cs.x * cd.x; c.y = cs.y * cd.y; c.z = cs.z * cd.z; c.w = cs.w * cd.w;
        *(uint2*)&g_CP[cp + col] = h4_pack(c);
    }
}

// ---------------- merged HMMA fp16 GEMM (BM=128, BN=64, BK=32, 8 warps) ---------
// R12 config (best measured). 3-stage cp.async, 1 sync/chunk, stateless indexing.
// Zero-weight skip: combined n-tiles 0-2 (chem cols, k<128 weights are zero)
// start at chunk 4 (the CP phase), removing 8.6% of combined MMA work exactly.
// blockIdx.x < 5 : combined (A=[SP via oidx | CP], K=896, B=g_WC, n0=x*64) -> g_acc
// blockIdx.x == 5: structural (A=g_SP, K=128, B=g_WS) -> g_ss / out
#define AS_P 2560   // 128 rows * 20 u32 (80B row stride, ldmatrix conflict-free)
#define BS_P 1280   // 64 rows * 20 u32
#define AS_B (AS_P * 4)
#define BS_B (BS_P * 4)
#define SMEM_U32 (3 * AS_P + 3 * BS_P + 128 + 128)
#define SMEM_BYTES (SMEM_U32 * 4)

__global__ void __launch_bounds__(256, 3) k_gemm(const float* __restrict__ sw2,
                                                 const float* __restrict__ sb2,
                                                 float* __restrict__ out)
{
    extern __shared__ uint32_t S[];
    uint32_t* Abase = S;
    uint32_t* Bbase = S + 3 * AS_P;
    float* rs = (float*)(S + 3 * AS_P + 3 * BS_P);
    int* oidx = (int*)(rs + 128);

    int tid = threadIdx.x, lane = tid & 31, wid = tid >> 5;
    int g = lane >> 2, tg = lane & 3;
    int wm = wid >> 1, wn = wid & 1;     // 4 row-groups (32 rows) x 2 col-groups

    const bool comb = (blockIdx.x < 5);
    int M, m0, n0, KCH, kstart;
    int m0raw = blockIdx.y * 128;
    if (comb) {
        M = g_count; m0 = m0raw;
        if (m0 >= M) return;
        n0 = blockIdx.x * 64; KCH = KTOT / 32;
        kstart = (blockIdx.x < 3) ? 4 : 0;   // chem cols: k<128 weights are zero
    } else {
        M = E_EDGES; m0 = m0raw; n0 = 0; KCH = SDIM / 32; kstart = 0;
    }

    if (tid < 128) {
        rs[tid] = 0.0f;
        if (comb) { int r = m0 + tid; oidx[tid] = (r < M) ? g_outidx[r] : g_outidx[0]; }
    }
    __syncthreads();

    uint32_t sA = smem_u32(Abase);
    uint32_t sB = smem_u32(Bbase);

    // ---- hoisted per-thread load assignments (advance 32 halfs = 64B per chunk)
    uint32_t aDst[2];
    const __half* aPtrS[2];   // SP-phase source (chunks 0..3 for comb; all for struct)
    const __half* aPtrC[2];   // CP-phase source (chunks 4.. for comb)
    #pragma unroll
    for (int i = 0; i < 2; i++) {
        int id = tid + i * 256;
        int row = id >> 2, u = id & 3;
        aDst[i] = sA + (row * 20 + u * 4) * 4;
        if (!comb) {
            int r = m0 + row; if (r >= E_EDGES) r = E_EDGES - 1;
            aPtrS[i] = g_SP + (size_t)r * SDIM + u * 8;
            aPtrC[i] = aPtrS[i];
        } else {
            aPtrS[i] = g_SP + (size_t)oidx[row] * SDIM + u * 8;
            int r = m0 + row; if (r >= M) r = 0;
            aPtrC[i] = g_CP + (size_t)r * CDIM + u * 8;
        }
    }
    uint32_t bDst;
    const __half* bPtr;
    {
        int row = tid >> 2, u = tid & 3;
        bDst = sB + (row * 20 + u * 4) * 4;
        bPtr = (!comb) ? (g_WS + (size_t)row * SDIM + u * 8)
                       : (g_WC + (size_t)(n0 + row) * KTOT + u * 8);
    }

    auto prefetch = [&](int c, int buf) {
        #pragma unroll
        for (int i = 0; i < 2; i++) {
            const __half* s = (c < 4) ? (aPtrS[i] + c * 32) : (aPtrC[i] + (c - 4) * 32);
            cp16(aDst[i] + (uint32_t)buf * AS_B, s);
        }
        cp16(bDst + (uint32_t)buf * BS_B, bPtr + c * 32);
        CP_COMMIT();
    };

    // ldmatrix lane addresses
    uint32_t aAddr = sA + (uint32_t)(wm * 32 + (lane & 15)) * 80 + ((lane >> 4) << 4);
    uint32_t bAddr = sB + (uint32_t)(wn * 32 + (lane & 7) + ((lane >> 4) << 3)) * 80
                        + (((lane >> 3) & 1) << 4);

    float acc[2][4][4];
    #pragma unroll
    for (int mi = 0; mi < 2; mi++)
        #pragma unroll
        for (int ni = 0; ni < 4; ni++)
            #pragma unroll
            for (int j = 0; j < 4; j++) acc[mi][ni][j] = 0.0f;

    prefetch(kstart, 0);
    if (KCH - kstart > 1) prefetch(kstart + 1, 1);

    int bc = 0;   // buffer of current chunk
    for (int c = kstart; c < KCH; c++) {
        if (c + 1 < KCH) CP_WAIT1(); else CP_WAIT0();
        __syncthreads();
        if (c + 2 < KCH) {
            int b2 = bc + 2; if (b2 >= 3) b2 -= 3;
            prefetch(c + 2, b2);
        }

        uint32_t aOff = (uint32_t)bc * AS_B;
        uint32_t bOff = (uint32_t)bc * BS_B;

        #pragma unroll
        for (int k16 = 0; k16 < 2; k16++) {
            uint32_t ka = aOff + k16 * 32;
            uint32_t kb = bOff + k16 * 32;
            uint32_t ah[2][4], bh[4][2];
            ldm_x4(ah[0], aAddr + ka);
            ldm_x4(ah[1], aAddr + ka + 1280);
            ldm_x4(&bh[0][0], bAddr + kb);
            ldm_x4(&bh[2][0], bAddr + kb + 1280);
            #pragma unroll
            for (int mi = 0; mi < 2; mi++)
                #pragma unroll
                for (int ni = 0; ni < 4; ni++)
                    mma_f16(acc[mi][ni], ah[mi], bh[ni]);
        }
        if (++bc == 3) bc = 0;
    }
    __syncthreads();

    // fused epilogue: relu(x + bias) dot weight-vector, reduced to per-row sums
    const float* bb = comb ? g_bC : g_bS;
    const float* vv = comb ? g_v2 : sw2;
    #pragma unroll
    for (int mi = 0; mi < 2; mi++) {
        float r0 = 0.f, r1 = 0.f;
        #pragma unroll
        for (int ni = 0; ni < 4; ni++) {
            int col = n0 + wn * 32 + ni * 8 + 2 * tg;
            float b0 = bb[col], b1 = bb[col + 1];
            float v0 = vv[col], v1 = vv[col + 1];
            r0 += fmaxf(acc[mi][ni][0] + b0, 0.f) * v0 + fmaxf(acc[mi][ni][1] + b1, 0.f) * v1;
            r1 += fmaxf(acc[mi][ni][2] + b0, 0.f) * v0 + fmaxf(acc[mi][ni][3] + b1, 0.f) * v1;
        }
        r0 += __shfl_xor_sync(0xffffffffu, r0, 1);
        r0 += __shfl_xor_sync(0xffffffffu, r0, 2);
        r1 += __shfl_xor_sync(0xffffffffu, r1, 1);
        r1 += __shfl_xor_sync(0xffffffffu, r1, 2);
        if (tg == 0) {
            atomicAdd(&rs[wm * 32 + mi * 16 + g], r0);
            atomicAdd(&rs[wm * 32 + mi * 16 + g + 8], r1);
        }
    }
    __syncthreads();

    if (tid < 128) {
        int row = m0 + tid;
        if (!comb) {
            if (row < E_EDGES) {
                float ss = rs[tid] + sb2[0];
                g_ss[row] = ss;
                if (!g_valid[row]) out[row] = ss;
            }
        } else {
            if (row < M) atomicAdd(&g_acc[row], rs[tid]);
        }
    }
}

// ---------------- final blend for valid edges ----------------
__global__ void k_final(const float* __restrict__ pw, const float* __restrict__ cb2,
                        const float* __restrict__ mb2, float* __restrict__ out)
{
    int idx = blockIdx.x * blockDim.x + threadIdx.x;
    if (idx >= g_count) return;
    float w0, w1, w2; softmax3(pw, w0, w1, w2);
    int e = g_outidx[idx];
    out[e] = w0 * g_ss[e] + g_acc[idx] + w1 * cb2[0] + w2 * mb2[0];
}

// ---------------- launcher (pack forked beside gather; single join) -------------
static cudaStream_t s_side = nullptr;
static cudaEvent_t s_e0 = nullptr, s_ePack = nullptr;

extern "C" void kernel_launch(void* const* d_in, const int* in_sizes, int n_in,
                              void* d_out, int out_size)
{
    const float* z    = (const float*)d_in[0];
    const float* chem = (const float*)d_in[1];
    const void*  edge = d_in[2];
    const int*   mask = (const int*)d_in[3];
    const float* sw1 = (const float*)d_in[4];
    const float* sb1 = (const float*)d_in[5];
    const float* sw2 = (const float*)d_in[6];
    const float* sb2 = (const float*)d_in[7];
    const float* cw1 = (const float*)d_in[8];
    const float* cb1 = (const float*)d_in[9];
    const float* cw2 = (const float*)d_in[10];
    const float* cb2 = (const float*)d_in[11];
    const float* mw1 = (const float*)d_in[12];
    const float* mb1 = (const float*)d_in[13];
    const float* mw2 = (const float*)d_in[14];
    const float* mb2 = (const float*)d_in[15];
    const float* pw  = (const float*)d_in[16];
    float* out = (float*)d_out;

    if (!s_side) {
        cudaStreamCreateWithFlags(&s_side, cudaStreamNonBlocking);
        cudaEventCreateWithFlags(&s_e0, cudaEventDisableTiming);
        cudaEventCreateWithFlags(&s_ePack, cudaEventDisableTiming);
        cudaFuncSetAttribute(k_gemm, cudaFuncAttributeMaxDynamicSharedMemorySize, SMEM_BYTES);
    }

    const int mtiles = (E_EDGES + 127) / 128;  // 1563
    cudaStream_t s0 = 0;

    k_zero<<<1, 32, 0, s0>>>(edge);
    cudaEventRecord(s_e0, s0);

    // side stream: weight pack, concurrent with the DRAM-bound gather
    cudaStreamWaitEvent(s_side, s_e0, 0);
    k_pack<<<1152, 256, 0, s_side>>>(cw1, cb1, cw2, mw1, mb1, mw2, sw1, sb1, pw);
    cudaEventRecord(s_ePack, s_side);

    // main stream: merged gather
    k_gather<<<(E_EDGES + 7) / 8, 256, 0, s0>>>(z, chem, edge, mask);

    // join, then merged GEMM + final
    cudaStreamWaitEvent(s0, s_ePack, 0);
    k_gemm<<<dim3(6, mtiles), 256, SMEM_BYTES, s0>>>(sw2, sb2, out);
    k_final<<<(E_EDGES + 255) / 256, 256, 0, s0>>>(pw, cb2, mb2, out);
}